// round 11
// baseline (speedup 1.0000x reference)
#include <cuda_runtime.h>

// filtfilt (5-tap butter-style IIR, odd ext padlen=15) over 512 rows, T=32768.
//
// R11 = R9's synchronous tile pipeline (cp.async in R10 cost 80 regs and
// 25% occ -> reverted) with R10's validated warm-up cut: WARM=32, CH=96,
// NCH=352 -> amplification (WARM+CH)/CH = 1.33 (was 1.60). Measured
// rel_err @ WARM=32 is 1.34e-4 (gate 1e-3): boundary error is attenuated
// by the second pass. Tile 0 is pure warm-up; tiles 1-3 fully emit (the
// partial-tile divergent branch from R9 disappears).
//  - phase-2 smem via LDS.128/STS.128 (TW=36 keeps 16B alignment),
//  - fwd phase-3 via LDS.128 + STG.128 (base = c0*96-32 = 0 mod 4),
//  - bwd descending stores stay scalar (parity-misaligned for vectors),
//  - WPB=4 (128-thread blocks, 18KB smem).
// Reference's per-row scale/descale is a linear no-op, skipped.

#define T_LEN     32768
#define PAD       15
#define TEXT      (T_LEN + 2 * PAD)   // 32798
#define ROWSTRIDE 32800
#define MAXROWS   512
#define NCH       352                 // chunks per row (11 * 32)
#define CH        96                  // NCH*CH = 33792 >= TEXT
#define WARM      32
#define WIN       (WARM + CH)         // 128
#define TILES     (WIN / 32)          // 4
#define WPR       11                  // warps per row
#define WPB       4                   // warps per block
#define BLOCK     (WPB * 32)          // 128
#define TW        36                  // tile row stride (floats), 16B multiple

#define LD128(p)    (*reinterpret_cast<const float4*>(p))
#define ST128(p, v) (*reinterpret_cast<float4*>(p) = (v))

__device__ float g_fwd[(size_t)MAXROWS * ROWSTRIDE];

struct Coef {
    float b0, b1, b2, b3, b4;
    float na1, na2, na3, na4;
};

__device__ __forceinline__ Coef load_coef(const float* __restrict__ bc,
                                          const float* __restrict__ ac) {
    Coef c;
    float inva0 = 1.0f / ac[0];
    c.b0 = bc[0] * inva0; c.b1 = bc[1] * inva0; c.b2 = bc[2] * inva0;
    c.b3 = bc[3] * inva0; c.b4 = bc[4] * inva0;
    c.na1 = -ac[1] * inva0; c.na2 = -ac[2] * inva0;
    c.na3 = -ac[3] * inva0; c.na4 = -ac[4] * inva0;
    return c;
}

// Direct-Form-I step; critical chain is the final fma through y1 (4 cyc).
#define IIR_STEP(xt)                                                   \
    do {                                                               \
        float f = fmaf(c.b0, (xt), fmaf(c.b1, x1,                      \
                  fmaf(c.b2, x2, fmaf(c.b3, x3, c.b4 * x4))));         \
        float s_ = fmaf(c.na2, y2, fmaf(c.na3, y3,                     \
                   fmaf(c.na4, y4, f)));                               \
        float y = fmaf(c.na1, y1, s_);                                 \
        x4 = x3; x3 = x2; x2 = x1; x1 = (xt);                          \
        y4 = y3; y3 = y2; y2 = y1; y1 = y;                             \
    } while (0)

// 8 IIR steps on one octet of the tile, optional store-back.
#define P2_OCTET(jb, do_store)                                         \
    do {                                                               \
        float4 va = LD128(&sm[lane][jb]);                              \
        float4 vb = LD128(&sm[lane][(jb) + 4]);                        \
        float4 wa, wb;                                                 \
        IIR_STEP(va.x); wa.x = y1; IIR_STEP(va.y); wa.y = y1;          \
        IIR_STEP(va.z); wa.z = y1; IIR_STEP(va.w); wa.w = y1;          \
        IIR_STEP(vb.x); wb.x = y1; IIR_STEP(vb.y); wb.y = y1;          \
        IIR_STEP(vb.z); wb.z = y1; IIR_STEP(vb.w); wb.w = y1;          \
        if (do_store) {                                                \
            ST128(&sm[lane][jb], wa);                                  \
            ST128(&sm[lane][(jb) + 4], wb);                            \
        }                                                              \
    } while (0)

__device__ __forceinline__ float load_xe_safe(const float* __restrict__ xr, int t) {
    if (t < 0)            return 0.0f;
    if (t < PAD)          return 2.0f * xr[0]         - xr[PAD - t];
    if (t < T_LEN + PAD)  return xr[t - PAD];
    if (t < TEXT)         return 2.0f * xr[T_LEN - 1] - xr[2 * T_LEN + PAD - 2 - t];
    return 0.0f;
}

__device__ __forceinline__ float load_rev_safe(const float* __restrict__ yr, int s) {
    if (s < 0 || s >= TEXT) return 0.0f;
    return yr[TEXT - 1 - s];
}

__global__ void __launch_bounds__(BLOCK)
fwd_kernel(const float* __restrict__ x,
           const float* __restrict__ bc,
           const float* __restrict__ ac) {
    int wib  = threadIdx.x >> 5;
    int lane = threadIdx.x & 31;
    int gw   = blockIdx.x * WPB + wib;
    int row  = gw / WPR;
    int wir  = gw - row * WPR;

    Coef c = load_coef(bc, ac);
    const float* xr = x + (size_t)row * T_LEN;
    float*       yr = g_fwd + (size_t)row * ROWSTRIDE;

    __shared__ float tile_s[WPB][32][TW];
    float (*sm)[TW] = tile_s[wib];

    int c0   = wir * 32;
    int base = c0 * CH - WARM;
    bool fast = (wir != 0) && (wir != WPR - 1);

    float x1 = 0.f, x2 = 0.f, x3 = 0.f, x4 = 0.f;
    float y1 = 0.f, y2 = 0.f, y3 = 0.f, y4 = 0.f;

    #pragma unroll
    for (int tl = 0; tl < TILES; ++tl) {
        int off = tl * 32;
        // Phase 1: coalesced transposed loads (sm[i][*] = chunk c0+i).
        if (fast) {
            const float* p = xr + (base - PAD) + off + lane;
            #pragma unroll 8
            for (int i = 0; i < 32; ++i) sm[i][lane] = p[i * CH];
        } else {
            #pragma unroll 4
            for (int i = 0; i < 32; ++i)
                sm[i][lane] = load_xe_safe(xr, base + i * CH + off + lane);
        }
        __syncwarp();
        // Phase 2: 32 IIR steps via 128-bit smem ops; tile 0 = pure warm-up.
        P2_OCTET(0,  tl >= 1);
        P2_OCTET(8,  tl >= 1);
        P2_OCTET(16, tl >= 1);
        P2_OCTET(24, tl >= 1);
        __syncwarp();
        // Phase 3: emitted-sample stores (tiles 1..3, fully emitted).
        if (tl >= 1) {
            if (fast) {
                int i0 = lane >> 3, q4 = (lane & 7) * 4;
                #pragma unroll
                for (int r8 = 0; r8 < 8; ++r8) {
                    int i = r8 * 4 + i0;
                    float4 v = LD128(&sm[i][q4]);
                    ST128(yr + base + i * CH + off + q4, v);
                }
            } else {
                #pragma unroll 4
                for (int i = 0; i < 32; ++i) {
                    int t = base + i * CH + off + lane;
                    if (t >= 0 && t < TEXT) yr[t] = sm[i][lane];
                }
            }
        }
        __syncwarp();
    }
}

__global__ void __launch_bounds__(BLOCK)
bwd_kernel(const float* __restrict__ bc,
           const float* __restrict__ ac,
           float* __restrict__ out) {
    int wib  = threadIdx.x >> 5;
    int lane = threadIdx.x & 31;
    int gw   = blockIdx.x * WPB + wib;
    int row  = gw / WPR;
    int wir  = gw - row * WPR;

    Coef c = load_coef(bc, ac);
    const float* yr   = g_fwd + (size_t)row * ROWSTRIDE;
    float*       orow = out   + (size_t)row * T_LEN;

    __shared__ float tile_s[WPB][32][TW];
    float (*sm)[TW] = tile_s[wib];

    int c0   = wir * 32;
    int base = c0 * CH - WARM;
    bool fast = (wir != 0) && (wir != WPR - 1);

    float x1 = 0.f, x2 = 0.f, x3 = 0.f, x4 = 0.f;
    float y1 = 0.f, y2 = 0.f, y3 = 0.f, y4 = 0.f;

    #pragma unroll
    for (int tl = 0; tl < TILES; ++tl) {
        int off = tl * 32;
        // Phase 1: reversed-time reads (descending-consecutive, coalesced).
        if (fast) {
            const float* p = yr + (TEXT - 1) - (base + off + lane);
            #pragma unroll 8
            for (int i = 0; i < 32; ++i) sm[i][lane] = p[-i * CH];
        } else {
            #pragma unroll 4
            for (int i = 0; i < 32; ++i)
                sm[i][lane] = load_rev_safe(yr, base + i * CH + off + lane);
        }
        __syncwarp();
        P2_OCTET(0,  tl >= 1);
        P2_OCTET(8,  tl >= 1);
        P2_OCTET(16, tl >= 1);
        P2_OCTET(24, tl >= 1);
        __syncwarp();
        // Phase 3: out position t = TEXT-1-s in crop [PAD, T+PAD)
        // -> s in [PAD, TEXT-1-PAD]; out idx (TEXT-1-PAD) - s (descending).
        if (tl >= 1) {
            if (fast) {
                float* q = orow + (TEXT - 1 - PAD) - (base + off + lane);
                #pragma unroll 8
                for (int i = 0; i < 32; ++i) q[-i * CH] = sm[i][lane];
            } else {
                #pragma unroll 4
                for (int i = 0; i < 32; ++i) {
                    int s = base + i * CH + off + lane;
                    if (s >= PAD && s <= TEXT - 1 - PAD)
                        orow[(TEXT - 1 - PAD) - s] = sm[i][lane];
                }
            }
        }
        __syncwarp();
    }
}

extern "C" void kernel_launch(void* const* d_in, const int* in_sizes, int n_in,
                              void* d_out, int out_size) {
    const float* x  = (const float*)d_in[0];
    const float* bc = (const float*)d_in[1];
    const float* ac = (const float*)d_in[2];
    float* out = (float*)d_out;

    int nrows  = in_sizes[0] / T_LEN;          // 512
    int total_warps = nrows * WPR;             // 5632
    int blocks = total_warps / WPB;            // 1408 (exact)

    fwd_kernel<<<blocks, BLOCK>>>(x, bc, ac);
    bwd_kernel<<<blocks, BLOCK>>>(bc, ac, out);
}

// round 12
// speedup vs baseline: 1.3371x; 1.3371x over previous
#include <cuda_runtime.h>

// filtfilt (5-tap butter-style IIR, odd ext padlen=15) over 512 rows, T=32768.
//
// R12: single-wave analysis — wall time tracks the per-warp critical path,
// not total work (R11 cut work 17% at constant 4 tiles/warp and did NOT get
// faster). So: shorten the per-warp path to 3 tiles (WARM=32, CH=64, WIN=96)
// and raise warp count to 8704 (NCH=544, WPR=17) so SMs stay filled
// (2176 blocks ~ 1.2 waves at the 12-block smem residency limit).
// rel_err @ WARM=32 measured 1.34e-4 (gate 1e-3).
//  - phase-2 smem via LDS.128/STS.128 (TW=36 keeps 16B alignment, and
//    lane-stride-36 phases hit distinct bank groups),
//  - fwd phase-3 via LDS.128 + STG.128 (base = c0*64-32 = 0 mod 4),
//  - bwd descending stores stay scalar (parity-misaligned for vectors),
//  - WPB=4 (128-thread blocks, 18KB smem).
// Reference's per-row scale/descale is a linear no-op, skipped.

#define T_LEN     32768
#define PAD       15
#define TEXT      (T_LEN + 2 * PAD)   // 32798
#define ROWSTRIDE 32800
#define MAXROWS   512
#define NCH       544                 // chunks per row (17 * 32)
#define CH        64                  // NCH*CH = 34816 >= TEXT
#define WARM      32
#define WIN       (WARM + CH)         // 96
#define TILES     (WIN / 32)          // 3
#define WPR       17                  // warps per row
#define WPB       4                   // warps per block
#define BLOCK     (WPB * 32)          // 128
#define TW        36                  // tile row stride (floats), 16B multiple

#define LD128(p)    (*reinterpret_cast<const float4*>(p))
#define ST128(p, v) (*reinterpret_cast<float4*>(p) = (v))

__device__ float g_fwd[(size_t)MAXROWS * ROWSTRIDE];

struct Coef {
    float b0, b1, b2, b3, b4;
    float na1, na2, na3, na4;
};

__device__ __forceinline__ Coef load_coef(const float* __restrict__ bc,
                                          const float* __restrict__ ac) {
    Coef c;
    float inva0 = 1.0f / ac[0];
    c.b0 = bc[0] * inva0; c.b1 = bc[1] * inva0; c.b2 = bc[2] * inva0;
    c.b3 = bc[3] * inva0; c.b4 = bc[4] * inva0;
    c.na1 = -ac[1] * inva0; c.na2 = -ac[2] * inva0;
    c.na3 = -ac[3] * inva0; c.na4 = -ac[4] * inva0;
    return c;
}

// Direct-Form-I step; critical chain is the final fma through y1 (4 cyc).
#define IIR_STEP(xt)                                                   \
    do {                                                               \
        float f = fmaf(c.b0, (xt), fmaf(c.b1, x1,                      \
                  fmaf(c.b2, x2, fmaf(c.b3, x3, c.b4 * x4))));         \
        float s_ = fmaf(c.na2, y2, fmaf(c.na3, y3,                     \
                   fmaf(c.na4, y4, f)));                               \
        float y = fmaf(c.na1, y1, s_);                                 \
        x4 = x3; x3 = x2; x2 = x1; x1 = (xt);                          \
        y4 = y3; y3 = y2; y2 = y1; y1 = y;                             \
    } while (0)

// 8 IIR steps on one octet of the tile, optional store-back.
#define P2_OCTET(jb, do_store)                                         \
    do {                                                               \
        float4 va = LD128(&sm[lane][jb]);                              \
        float4 vb = LD128(&sm[lane][(jb) + 4]);                        \
        float4 wa, wb;                                                 \
        IIR_STEP(va.x); wa.x = y1; IIR_STEP(va.y); wa.y = y1;          \
        IIR_STEP(va.z); wa.z = y1; IIR_STEP(va.w); wa.w = y1;          \
        IIR_STEP(vb.x); wb.x = y1; IIR_STEP(vb.y); wb.y = y1;          \
        IIR_STEP(vb.z); wb.z = y1; IIR_STEP(vb.w); wb.w = y1;          \
        if (do_store) {                                                \
            ST128(&sm[lane][jb], wa);                                  \
            ST128(&sm[lane][(jb) + 4], wb);                            \
        }                                                              \
    } while (0)

__device__ __forceinline__ float load_xe_safe(const float* __restrict__ xr, int t) {
    if (t < 0)            return 0.0f;
    if (t < PAD)          return 2.0f * xr[0]         - xr[PAD - t];
    if (t < T_LEN + PAD)  return xr[t - PAD];
    if (t < TEXT)         return 2.0f * xr[T_LEN - 1] - xr[2 * T_LEN + PAD - 2 - t];
    return 0.0f;
}

__device__ __forceinline__ float load_rev_safe(const float* __restrict__ yr, int s) {
    if (s < 0 || s >= TEXT) return 0.0f;
    return yr[TEXT - 1 - s];
}

__global__ void __launch_bounds__(BLOCK)
fwd_kernel(const float* __restrict__ x,
           const float* __restrict__ bc,
           const float* __restrict__ ac) {
    int wib  = threadIdx.x >> 5;
    int lane = threadIdx.x & 31;
    int gw   = blockIdx.x * WPB + wib;
    int row  = gw / WPR;
    int wir  = gw - row * WPR;

    Coef c = load_coef(bc, ac);
    const float* xr = x + (size_t)row * T_LEN;
    float*       yr = g_fwd + (size_t)row * ROWSTRIDE;

    __shared__ float tile_s[WPB][32][TW];
    float (*sm)[TW] = tile_s[wib];

    int c0   = wir * 32;
    int base = c0 * CH - WARM;
    bool fast = (wir != 0) && (wir != WPR - 1);

    float x1 = 0.f, x2 = 0.f, x3 = 0.f, x4 = 0.f;
    float y1 = 0.f, y2 = 0.f, y3 = 0.f, y4 = 0.f;

    #pragma unroll
    for (int tl = 0; tl < TILES; ++tl) {
        int off = tl * 32;
        // Phase 1: coalesced transposed loads (sm[i][*] = chunk c0+i).
        if (fast) {
            const float* p = xr + (base - PAD) + off + lane;
            #pragma unroll 8
            for (int i = 0; i < 32; ++i) sm[i][lane] = p[i * CH];
        } else {
            #pragma unroll 4
            for (int i = 0; i < 32; ++i)
                sm[i][lane] = load_xe_safe(xr, base + i * CH + off + lane);
        }
        __syncwarp();
        // Phase 2: 32 IIR steps via 128-bit smem ops; tile 0 = pure warm-up.
        P2_OCTET(0,  tl >= 1);
        P2_OCTET(8,  tl >= 1);
        P2_OCTET(16, tl >= 1);
        P2_OCTET(24, tl >= 1);
        __syncwarp();
        // Phase 3: emitted-sample stores (tiles 1..2, fully emitted).
        if (tl >= 1) {
            if (fast) {
                int i0 = lane >> 3, q4 = (lane & 7) * 4;
                #pragma unroll
                for (int r8 = 0; r8 < 8; ++r8) {
                    int i = r8 * 4 + i0;
                    float4 v = LD128(&sm[i][q4]);
                    ST128(yr + base + i * CH + off + q4, v);
                }
            } else {
                #pragma unroll 4
                for (int i = 0; i < 32; ++i) {
                    int t = base + i * CH + off + lane;
                    if (t >= 0 && t < TEXT) yr[t] = sm[i][lane];
                }
            }
        }
        __syncwarp();
    }
}

__global__ void __launch_bounds__(BLOCK)
bwd_kernel(const float* __restrict__ bc,
           const float* __restrict__ ac,
           float* __restrict__ out) {
    int wib  = threadIdx.x >> 5;
    int lane = threadIdx.x & 31;
    int gw   = blockIdx.x * WPB + wib;
    int row  = gw / WPR;
    int wir  = gw - row * WPR;

    Coef c = load_coef(bc, ac);
    const float* yr   = g_fwd + (size_t)row * ROWSTRIDE;
    float*       orow = out   + (size_t)row * T_LEN;

    __shared__ float tile_s[WPB][32][TW];
    float (*sm)[TW] = tile_s[wib];

    int c0   = wir * 32;
    int base = c0 * CH - WARM;
    bool fast = (wir != 0) && (wir != WPR - 1);

    float x1 = 0.f, x2 = 0.f, x3 = 0.f, x4 = 0.f;
    float y1 = 0.f, y2 = 0.f, y3 = 0.f, y4 = 0.f;

    #pragma unroll
    for (int tl = 0; tl < TILES; ++tl) {
        int off = tl * 32;
        // Phase 1: reversed-time reads (descending-consecutive, coalesced).
        if (fast) {
            const float* p = yr + (TEXT - 1) - (base + off + lane);
            #pragma unroll 8
            for (int i = 0; i < 32; ++i) sm[i][lane] = p[-i * CH];
        } else {
            #pragma unroll 4
            for (int i = 0; i < 32; ++i)
                sm[i][lane] = load_rev_safe(yr, base + i * CH + off + lane);
        }
        __syncwarp();
        P2_OCTET(0,  tl >= 1);
        P2_OCTET(8,  tl >= 1);
        P2_OCTET(16, tl >= 1);
        P2_OCTET(24, tl >= 1);
        __syncwarp();
        // Phase 3: out position t = TEXT-1-s in crop [PAD, T+PAD)
        // -> s in [PAD, TEXT-1-PAD]; out idx (TEXT-1-PAD) - s (descending).
        if (tl >= 1) {
            if (fast) {
                float* q = orow + (TEXT - 1 - PAD) - (base + off + lane);
                #pragma unroll 8
                for (int i = 0; i < 32; ++i) q[-i * CH] = sm[i][lane];
            } else {
                #pragma unroll 4
                for (int i = 0; i < 32; ++i) {
                    int s = base + i * CH + off + lane;
                    if (s >= PAD && s <= TEXT - 1 - PAD)
                        orow[(TEXT - 1 - PAD) - s] = sm[i][lane];
                }
            }
        }
        __syncwarp();
    }
}

extern "C" void kernel_launch(void* const* d_in, const int* in_sizes, int n_in,
                              void* d_out, int out_size) {
    const float* x  = (const float*)d_in[0];
    const float* bc = (const float*)d_in[1];
    const float* ac = (const float*)d_in[2];
    float* out = (float*)d_out;

    int nrows  = in_sizes[0] / T_LEN;          // 512
    int total_warps = nrows * WPR;             // 8704
    int blocks = total_warps / WPB;            // 2176 (exact)

    fwd_kernel<<<blocks, BLOCK>>>(x, bc, ac);
    bwd_kernel<<<blocks, BLOCK>>>(bc, ac, out);
}